// round 1
// baseline (speedup 1.0000x reference)
#include <cuda_runtime.h>
#include <math.h>
#include <float.h>

#define NB 1024   // batch
#define LL 4096   // simulated length
#define PP 8192   // acquired length
#define NT 512    // threads per CTA
#define SPT 8     // L elements per thread (LL / NT)

// Twiddle table: exp(-2*pi*i*j/PP), j in [0, PP/2)
__device__ float2 d_tw[PP / 2];

__global__ void init_tw_kernel() {
    int j = blockIdx.x * blockDim.x + threadIdx.x;
    if (j < PP / 2) {
        float ang = -6.28318530717958647692f * (float)j / (float)PP;
        float s, c;
        sincosf(ang, &s, &c);
        d_tw[j] = make_float2(c, s);
    }
}

// ---- block-wide helpers (512 threads = 16 warps). ws must hold >= 17 floats.
__device__ __forceinline__ float block_scan_inclusive(float v, float* ws, int tid) {
    __syncthreads();  // protect ws from previous use
    int lane = tid & 31, wp = tid >> 5;
    float x = v;
#pragma unroll
    for (int d = 1; d < 32; d <<= 1) {
        float y = __shfl_up_sync(0xffffffffu, x, d);
        if (lane >= d) x += y;
    }
    if (lane == 31) ws[wp] = x;
    __syncthreads();
    if (wp == 0) {
        float t = (lane < 16) ? ws[lane] : 0.f;
#pragma unroll
        for (int d = 1; d < 16; d <<= 1) {
            float y = __shfl_up_sync(0xffffffffu, t, d);
            if (lane >= d) t += y;
        }
        if (lane < 16) ws[lane] = t;
    }
    __syncthreads();
    float off = (wp > 0) ? ws[wp - 1] : 0.f;
    return x + off;
}

__device__ __forceinline__ float block_reduce_max(float v, float* ws, int tid) {
    __syncthreads();
    int lane = tid & 31, wp = tid >> 5;
#pragma unroll
    for (int d = 16; d > 0; d >>= 1) v = fmaxf(v, __shfl_xor_sync(0xffffffffu, v, d));
    if (lane == 0) ws[wp] = v;
    __syncthreads();
    if (wp == 0) {
        float t = (lane < 16) ? ws[lane] : -FLT_MAX;
#pragma unroll
        for (int d = 8; d > 0; d >>= 1) t = fmaxf(t, __shfl_xor_sync(0xffffffffu, t, d));
        if (lane == 0) ws[16] = t;
    }
    __syncthreads();
    return ws[16];
}

__device__ __forceinline__ float block_reduce_min(float v, float* ws, int tid) {
    __syncthreads();
    int lane = tid & 31, wp = tid >> 5;
#pragma unroll
    for (int d = 16; d > 0; d >>= 1) v = fminf(v, __shfl_xor_sync(0xffffffffu, v, d));
    if (lane == 0) ws[wp] = v;
    __syncthreads();
    if (wp == 0) {
        float t = (lane < 16) ? ws[lane] : FLT_MAX;
#pragma unroll
        for (int d = 8; d > 0; d >>= 1) t = fminf(t, __shfl_xor_sync(0xffffffffu, t, d));
        if (lane == 0) ws[16] = t;
    }
    __syncthreads();
    return ws[16];
}

// One CTA handles rows (2g, 2g+1); the pair shares one complex FFT.
__global__ void __launch_bounds__(NT, 2)
pipeline_kernel(const float* __restrict__ g_start, const float* __restrict__ g_end,
                const float* __restrict__ g_std,   const float* __restrict__ g_lb,
                const float* __restrict__ g_ub,    const int*   __restrict__ g_win,
                const float* __restrict__ g_scale, const float* __restrict__ g_noise,
                const float* __restrict__ g_omit,  const float* __restrict__ g_ppm,
                const float* __restrict__ g_range, float* __restrict__ out)
{
    extern __shared__ char smem_raw[];
    float2* sf  = (float2*)smem_raw;                            // PP complex = 64 KB
    float*  sw  = (float*)(smem_raw + sizeof(float2) * PP);     // LL floats
    float*  scs = sw + LL;                                      // LL+1 floats
    float*  red = scs + (LL + 1);                               // 32 floats scratch

    const int tid = threadIdx.x;
    const int g   = blockIdx.x;
    const float inv_lm1 = 1.0f / (float)(LL - 1);
    const float rlo = g_range[0], rhi = g_range[1];
    const size_t raw_off = (size_t)NB * 2 * PP;   // second tensor in the output tuple

    for (int hh = 0; hh < 2; ++hh) {
        const int r = 2 * g + hh;
        const int base = tid * SPT;

        // ---- bounded random walk: rand = cumsum(std*(noise-0.5)) ----
        const float sd = g_std[r];
        const float* nz = g_noise + (size_t)r * LL + base;
        float4 v0 = *(const float4*)(nz);
        float4 v1 = *(const float4*)(nz + 4);
        float vv[SPT] = {v0.x, v0.y, v0.z, v0.w, v1.x, v1.y, v1.z, v1.w};
        float loc[SPT];
        {
            float a = 0.f;
#pragma unroll
            for (int j = 0; j < SPT; ++j) { a += sd * (vv[j] - 0.5f); loc[j] = a; }
        }
        float excl;
        {
            float incl = block_scan_inclusive(loc[SPT - 1], red, tid);
            excl = incl - loc[SPT - 1];
        }
#pragma unroll
        for (int j = 0; j < SPT; ++j) sw[base + j] = loc[j] + excl;
        __syncthreads();

        const float r0 = sw[0], rl = sw[LL - 1];

        // detrended deltas + min/max
        float dmx = -FLT_MAX, dmn = FLT_MAX;
        float del[SPT];
#pragma unroll
        for (int j = 0; j < SPT; ++j) {
            int t = base + j;
            float ft = (float)t * inv_lm1;
            float d = (loc[j] + excl) - (r0 + (rl - r0) * ft);
            del[j] = d;
            dmx = fmaxf(dmx, d);
            dmn = fminf(dmn, d);
        }
        dmx = block_reduce_max(dmx, red, tid);
        dmn = block_reduce_min(dmn, red, tid);

        const float lo_b = g_lb[r], hi_b = g_ub[r];
        const float bounds = hi_b - lo_b;
        const float dv = fmaxf(1.0f, (dmx - dmn) / bounds);
        const float invdv = 1.0f / dv;
        const float st_ = g_start[r], en_ = g_end[r];

        // squeeze + reflect + add trend => walk (kept in regs)
        float wk[SPT];
#pragma unroll
        for (int j = 0; j < SPT; ++j) {
            int t = base + j;
            float ft = (float)t * inv_lm1;
            float d = del[j] * invdv;
            float tr = st_ + (en_ - st_) * ft;
            float ub2 = hi_b - tr, lb2 = lo_b - tr;
            float over = d - ub2;
            if (over >= 0.f) d = ub2 - over;
            float under = lb2 - d;
            if (under >= 0.f) d = lb2 + under;
            wk[j] = tr + d;
        }

        // ---- cumsum(walk) -> scs[0..LL], scs[0] = 0 ----
        float pre[SPT];
        {
            float a = 0.f;
#pragma unroll
            for (int j = 0; j < SPT; ++j) { a += wk[j]; pre[j] = a; }
        }
        {
            float incl = block_scan_inclusive(pre[SPT - 1], red, tid);
            float ex2 = incl - pre[SPT - 1];
#pragma unroll
            for (int j = 0; j < SPT; ++j) scs[1 + base + j] = pre[j] + ex2;
        }
        if (tid == 0) scs[0] = 0.f;
        __syncthreads();

        // ---- box smooth via cumsum difference (zero padding == clamp) ----
        const int w = g_win[r];
        const float invw = 1.0f / (float)w;
        const int wh = w >> 1;
#pragma unroll
        for (int j = 0; j < SPT; ++j) {
            int t = base + j;
            int lo = t - wh;
            int hi = lo + w;
            lo = max(lo, 0);
            hi = min(hi, LL);
            sw[t] = (scs[hi] - scs[lo]) * invw;
        }
        __syncthreads();

        // ---- detrend b, normalize by max|.|, apply omit*scale ----
        const float b0 = sw[0], bl = sw[LL - 1];
        float mab = 0.f;
        float cc[SPT];
#pragma unroll
        for (int j = 0; j < SPT; ++j) {
            int t = base + j;
            float ft = (float)t * inv_lm1;
            float c = sw[t] - (b0 + (bl - b0) * ft);
            cc[j] = c;
            mab = fmaxf(mab, fabsf(c));
        }
        mab = block_reduce_max(mab, red, tid);
        const float denom = (mab == 0.f) ? 1.0f : mab;
        const float fac = g_omit[r] * g_scale[r] / denom;
#pragma unroll
        for (int j = 0; j < SPT; ++j) sw[base + j] = cc[j] * fac;
        __syncthreads();

        // ---- interp onto ppm axis; write real channel; fill FFT buffer ----
        const float istep = (float)(LL - 1) / (rhi - rlo);
        const size_t och = ((size_t)r * 2) * PP;  // channel 0 of row r
        for (int p = tid; p < PP; p += NT) {
            float xp = g_ppm[p];
            float v = 0.f;
            if (xp >= rlo && xp <= rhi) {
                float u = (xp - rlo) * istep;
                int i = (int)u;
                if (i > LL - 2) i = LL - 2;
                float f = u - (float)i;
                float s0 = sw[i], s1 = sw[i + 1];
                v = fmaf(s1 - s0, f, s0);
            }
            if (hh == 0) sf[p].x = v;
            else         sf[p].y = v;
            out[och + (PP - 1 - p)] = v;       // flipped tensor (first)
            out[raw_off + och + p] = v;        // raw tensor (second)
        }
        __syncthreads();
    }

    // ================= Hilbert of both rows via one complex FFT =================
    // forward radix-2 DIF (natural -> bit-reversed)
    {
        int lh = 12;
#pragma unroll 1
        for (int s = 0; s < 13; ++s) {
            const int hl = 1 << lh;
            const int ts = 12 - lh;
            for (int j = tid; j < PP / 2; j += NT) {
                int off = j & (hl - 1);
                int i0 = ((j >> lh) << (lh + 1)) | off;
                int i1 = i0 + hl;
                float2 a = sf[i0], b = sf[i1];
                float2 tw = d_tw[off << ts];
                float dx = a.x - b.x, dy = a.y - b.y;
                sf[i0] = make_float2(a.x + b.x, a.y + b.y);
                sf[i1] = make_float2(dx * tw.x - dy * tw.y, dx * tw.y + dy * tw.x);
            }
            __syncthreads();
            --lh;
        }
    }

    // spectral multiply by -i*sgn(k) in bit-reversed position space:
    // p==0 -> k=0 (zero); p==1 -> k=P/2 (zero); p even -> 0<k<P/2 (-i*z); p odd -> k>P/2 (+i*z)
    for (int p = tid; p < PP; p += NT) {
        float2 z = sf[p];
        float2 o;
        if (p <= 1)       o = make_float2(0.f, 0.f);
        else if (p & 1)   o = make_float2(-z.y, z.x);
        else              o = make_float2(z.y, -z.x);
        sf[p] = o;
    }
    __syncthreads();

    // inverse radix-2 DIT (bit-reversed -> natural), twiddle = conj(d_tw)
    {
        int lh = 0;
#pragma unroll 1
        for (int s = 0; s < 13; ++s) {
            const int hl = 1 << lh;
            const int ts = 12 - lh;
            for (int j = tid; j < PP / 2; j += NT) {
                int off = j & (hl - 1);
                int i0 = ((j >> lh) << (lh + 1)) | off;
                int i1 = i0 + hl;
                float2 tw = d_tw[off << ts];
                float2 a = sf[i0], b = sf[i1];
                float tx = b.x * tw.x + b.y * tw.y;
                float ty = b.y * tw.x - b.x * tw.y;
                sf[i0] = make_float2(a.x + tx, a.y + ty);
                sf[i1] = make_float2(a.x - tx, a.y - ty);
            }
            __syncthreads();
            ++lh;
        }
    }

    // write Hilbert channel for both rows (real part -> row 2g, imag -> row 2g+1)
    const float invP = 1.0f / (float)PP;
    const size_t ch1a = ((size_t)(2 * g) * 2 + 1) * PP;
    const size_t ch1b = ((size_t)(2 * g + 1) * 2 + 1) * PP;
    for (int p = tid; p < PP; p += NT) {
        float2 h = sf[p];
        float hA = h.x * invP;
        float hB = h.y * invP;
        out[ch1a + (PP - 1 - p)] = hA;
        out[raw_off + ch1a + p] = hA;
        out[ch1b + (PP - 1 - p)] = hB;
        out[raw_off + ch1b + p] = hB;
    }
}

extern "C" void kernel_launch(void* const* d_in, const int* in_sizes, int n_in,
                              void* d_out, int out_size) {
    const float* g_start = (const float*)d_in[0];
    const float* g_end   = (const float*)d_in[1];
    const float* g_std   = (const float*)d_in[2];
    const float* g_lb    = (const float*)d_in[3];
    const float* g_ub    = (const float*)d_in[4];
    const int*   g_win   = (const int*)  d_in[5];
    const float* g_scale = (const float*)d_in[6];
    const float* g_noise = (const float*)d_in[7];
    const float* g_omit  = (const float*)d_in[8];
    const float* g_ppm   = (const float*)d_in[9];
    const float* g_range = (const float*)d_in[10];
    float* out = (float*)d_out;

    init_tw_kernel<<<(PP / 2 + 511) / 512, 512>>>();

    size_t smem = sizeof(float2) * PP + sizeof(float) * (LL + (LL + 1) + 64);
    cudaFuncSetAttribute(pipeline_kernel,
                         cudaFuncAttributeMaxDynamicSharedMemorySize, (int)smem);
    pipeline_kernel<<<NB / 2, NT, smem>>>(
        g_start, g_end, g_std, g_lb, g_ub, g_win, g_scale, g_noise,
        g_omit, g_ppm, g_range, out);
}

// round 2
// speedup vs baseline: 2.9456x; 2.9456x over previous
#include <cuda_runtime.h>
#include <math.h>
#include <float.h>

#define NB 1024   // batch
#define LL 4096   // simulated length
#define PP 8192   // acquired length
#define NT 512    // threads per CTA
#define SPT 8     // L elements per thread (LL / NT)
#define PAD(i) ((i) + ((i) >> 4))

// Twiddle table: exp(-2*pi*i*j/PP), j in [0, PP/2)
__device__ float2 d_tw[PP / 2];

__global__ void init_tw_kernel() {
    int j = blockIdx.x * blockDim.x + threadIdx.x;
    if (j < PP / 2) {
        float ang = -6.28318530717958647692f * (float)j / (float)PP;
        float s, c;
        sincosf(ang, &s, &c);
        d_tw[j] = make_float2(c, s);
    }
}

__device__ __forceinline__ float2 cmulf(float2 a, float2 b) {
    return make_float2(a.x * b.x - a.y * b.y, a.x * b.y + a.y * b.x);
}

// 16-point DFT, DIF network: natural-order inputs in z[0..15],
// outputs y_r = z[bitrev4(r)].  INV=false: forward (W^-), INV=true: inverse (W^+).
template<bool INV>
__device__ __forceinline__ void dft16_dif(float2* z) {
    const float s = INV ? 1.0f : -1.0f;
    const float C1 = 0.92387953251128674f, S1 = 0.38268343236508978f, R2 = 0.70710678118654752f;
#define BF1(i0,i1) { float ax=z[i0].x-z[i1].x, ay=z[i0].y-z[i1].y; z[i0].x+=z[i1].x; z[i0].y+=z[i1].y; z[i1].x=ax; z[i1].y=ay; }
#define BFI(i0,i1) { float ax=z[i0].x-z[i1].x, ay=z[i0].y-z[i1].y; z[i0].x+=z[i1].x; z[i0].y+=z[i1].y; z[i1].x=-s*ay; z[i1].y=s*ax; }
#define BFT(i0,i1,tc,ts) { float ax=z[i0].x-z[i1].x, ay=z[i0].y-z[i1].y; z[i0].x+=z[i1].x; z[i0].y+=z[i1].y; z[i1].x=ax*(tc)-ay*(ts); z[i1].y=ax*(ts)+ay*(tc); }
    // stage h=8, twiddles W16^i
    BF1(0, 8); BFT(1, 9, C1, s * S1); BFT(2, 10, R2, s * R2); BFT(3, 11, S1, s * C1);
    BFI(4, 12); BFT(5, 13, -S1, s * C1); BFT(6, 14, -R2, s * R2); BFT(7, 15, -C1, s * S1);
    // stage h=4, twiddles W8^i
    BF1(0, 4); BFT(1, 5, R2, s * R2); BFI(2, 6); BFT(3, 7, -R2, s * R2);
    BF1(8, 12); BFT(9, 13, R2, s * R2); BFI(10, 14); BFT(11, 15, -R2, s * R2);
    // stage h=2, twiddles W4^i
    BF1(0, 2); BFI(1, 3); BF1(4, 6); BFI(5, 7);
    BF1(8, 10); BFI(9, 11); BF1(12, 14); BFI(13, 15);
    // stage h=1
    BF1(0, 1); BF1(2, 3); BF1(4, 5); BF1(6, 7);
    BF1(8, 9); BF1(10, 11); BF1(12, 13); BF1(14, 15);
#undef BF1
#undef BFI
#undef BFT
}

// 16-point DFT, DIT network: bit-reversed inputs (z[k] = x[bitrev4(k)]),
// natural-order outputs z[r] = y_r.
template<bool INV>
__device__ __forceinline__ void dft16_dit(float2* z) {
    const float s = INV ? 1.0f : -1.0f;
    const float C1 = 0.92387953251128674f, S1 = 0.38268343236508978f, R2 = 0.70710678118654752f;
#define BT1(i0,i1) { float bx=z[i1].x, by=z[i1].y; z[i1].x=z[i0].x-bx; z[i1].y=z[i0].y-by; z[i0].x+=bx; z[i0].y+=by; }
#define BTI(i0,i1) { float bx=-s*z[i1].y, by=s*z[i1].x; z[i1].x=z[i0].x-bx; z[i1].y=z[i0].y-by; z[i0].x+=bx; z[i0].y+=by; }
#define BTT(i0,i1,tc,ts) { float bx=z[i1].x*(tc)-z[i1].y*(ts), by=z[i1].x*(ts)+z[i1].y*(tc); z[i1].x=z[i0].x-bx; z[i1].y=z[i0].y-by; z[i0].x+=bx; z[i0].y+=by; }
    // stage h=1
    BT1(0, 1); BT1(2, 3); BT1(4, 5); BT1(6, 7);
    BT1(8, 9); BT1(10, 11); BT1(12, 13); BT1(14, 15);
    // stage h=2, tw W4^j
    BT1(0, 2); BTI(1, 3); BT1(4, 6); BTI(5, 7);
    BT1(8, 10); BTI(9, 11); BT1(12, 14); BTI(13, 15);
    // stage h=4, tw W8^j
    BT1(0, 4); BTT(1, 5, R2, s * R2); BTI(2, 6); BTT(3, 7, -R2, s * R2);
    BT1(8, 12); BTT(9, 13, R2, s * R2); BTI(10, 14); BTT(11, 15, -R2, s * R2);
    // stage h=8, tw W16^j
    BT1(0, 8); BTT(1, 9, C1, s * S1); BTT(2, 10, R2, s * R2); BTT(3, 11, S1, s * C1);
    BTI(4, 12); BTT(5, 13, -S1, s * C1); BTT(6, 14, -R2, s * R2); BTT(7, 15, -C1, s * S1);
#undef BT1
#undef BTI
#undef BTT
}

// ---- block-wide helpers (512 threads = 16 warps). ws must hold >= 17 floats.
__device__ __forceinline__ float block_scan_inclusive(float v, float* ws, int tid) {
    __syncthreads();
    int lane = tid & 31, wp = tid >> 5;
    float x = v;
#pragma unroll
    for (int d = 1; d < 32; d <<= 1) {
        float y = __shfl_up_sync(0xffffffffu, x, d);
        if (lane >= d) x += y;
    }
    if (lane == 31) ws[wp] = x;
    __syncthreads();
    if (wp == 0) {
        float t = (lane < 16) ? ws[lane] : 0.f;
#pragma unroll
        for (int d = 1; d < 16; d <<= 1) {
            float y = __shfl_up_sync(0xffffffffu, t, d);
            if (lane >= d) t += y;
        }
        if (lane < 16) ws[lane] = t;
    }
    __syncthreads();
    float off = (wp > 0) ? ws[wp - 1] : 0.f;
    return x + off;
}

__device__ __forceinline__ float block_reduce_max(float v, float* ws, int tid) {
    __syncthreads();
    int lane = tid & 31, wp = tid >> 5;
#pragma unroll
    for (int d = 16; d > 0; d >>= 1) v = fmaxf(v, __shfl_xor_sync(0xffffffffu, v, d));
    if (lane == 0) ws[wp] = v;
    __syncthreads();
    if (wp == 0) {
        float t = (lane < 16) ? ws[lane] : -FLT_MAX;
#pragma unroll
        for (int d = 8; d > 0; d >>= 1) t = fmaxf(t, __shfl_xor_sync(0xffffffffu, t, d));
        if (lane == 0) ws[16] = t;
    }
    __syncthreads();
    return ws[16];
}

__device__ __forceinline__ float block_reduce_min(float v, float* ws, int tid) {
    __syncthreads();
    int lane = tid & 31, wp = tid >> 5;
#pragma unroll
    for (int d = 16; d > 0; d >>= 1) v = fminf(v, __shfl_xor_sync(0xffffffffu, v, d));
    if (lane == 0) ws[wp] = v;
    __syncthreads();
    if (wp == 0) {
        float t = (lane < 16) ? ws[lane] : FLT_MAX;
#pragma unroll
        for (int d = 8; d > 0; d >>= 1) t = fminf(t, __shfl_xor_sync(0xffffffffu, t, d));
        if (lane == 0) ws[16] = t;
    }
    __syncthreads();
    return ws[16];
}

// One CTA handles rows (2g, 2g+1); the pair shares one complex FFT.
__global__ void __launch_bounds__(NT, 2)
pipeline_kernel(const float* __restrict__ g_start, const float* __restrict__ g_end,
                const float* __restrict__ g_std,   const float* __restrict__ g_lb,
                const float* __restrict__ g_ub,    const int*   __restrict__ g_win,
                const float* __restrict__ g_scale, const float* __restrict__ g_noise,
                const float* __restrict__ g_omit,  const float* __restrict__ g_ppm,
                const float* __restrict__ g_range, float* __restrict__ out)
{
    extern __shared__ char smem_raw[];
    float2* sf  = (float2*)smem_raw;                            // PAD(8192) = 8704 float2 = 69632 B
    float*  sw  = (float*)(smem_raw + 69632);                   // LL floats
    float*  scs = sw + LL;                                      // LL+1 floats
    float*  red = scs + (LL + 1);                               // 32 floats scratch

    const int tid = threadIdx.x;
    const int g   = blockIdx.x;
    const float inv_lm1 = 1.0f / (float)(LL - 1);
    const float rlo = g_range[0], rhi = g_range[1];
    const size_t raw_off = (size_t)NB * 2 * PP;
    const int rv[16] = {0, 8, 4, 12, 2, 10, 6, 14, 1, 9, 5, 13, 3, 11, 7, 15};

    for (int hh = 0; hh < 2; ++hh) {
        const int r = 2 * g + hh;
        const int base = tid * SPT;

        // ---- bounded random walk: rand = cumsum(std*(noise-0.5)) ----
        const float sd = g_std[r];
        const float* nz = g_noise + (size_t)r * LL + base;
        float4 v0 = *(const float4*)(nz);
        float4 v1 = *(const float4*)(nz + 4);
        float vv[SPT] = {v0.x, v0.y, v0.z, v0.w, v1.x, v1.y, v1.z, v1.w};
        float loc[SPT];
        {
            float a = 0.f;
#pragma unroll
            for (int j = 0; j < SPT; ++j) { a += sd * (vv[j] - 0.5f); loc[j] = a; }
        }
        float excl;
        {
            float incl = block_scan_inclusive(loc[SPT - 1], red, tid);
            excl = incl - loc[SPT - 1];
        }
#pragma unroll
        for (int j = 0; j < SPT; ++j) sw[base + j] = loc[j] + excl;
        __syncthreads();

        const float r0 = sw[0], rl = sw[LL - 1];

        float dmx = -FLT_MAX, dmn = FLT_MAX;
        float del[SPT];
#pragma unroll
        for (int j = 0; j < SPT; ++j) {
            int t = base + j;
            float ft = (float)t * inv_lm1;
            float d = (loc[j] + excl) - (r0 + (rl - r0) * ft);
            del[j] = d;
            dmx = fmaxf(dmx, d);
            dmn = fminf(dmn, d);
        }
        dmx = block_reduce_max(dmx, red, tid);
        dmn = block_reduce_min(dmn, red, tid);

        const float lo_b = g_lb[r], hi_b = g_ub[r];
        const float bounds = hi_b - lo_b;
        const float dv = fmaxf(1.0f, (dmx - dmn) / bounds);
        const float invdv = 1.0f / dv;
        const float st_ = g_start[r], en_ = g_end[r];

        float wk[SPT];
#pragma unroll
        for (int j = 0; j < SPT; ++j) {
            int t = base + j;
            float ft = (float)t * inv_lm1;
            float d = del[j] * invdv;
            float tr = st_ + (en_ - st_) * ft;
            float ub2 = hi_b - tr, lb2 = lo_b - tr;
            float over = d - ub2;
            if (over >= 0.f) d = ub2 - over;
            float under = lb2 - d;
            if (under >= 0.f) d = lb2 + under;
            wk[j] = tr + d;
        }

        // ---- cumsum(walk) -> scs[0..LL] ----
        float pre[SPT];
        {
            float a = 0.f;
#pragma unroll
            for (int j = 0; j < SPT; ++j) { a += wk[j]; pre[j] = a; }
        }
        {
            float incl = block_scan_inclusive(pre[SPT - 1], red, tid);
            float ex2 = incl - pre[SPT - 1];
#pragma unroll
            for (int j = 0; j < SPT; ++j) scs[1 + base + j] = pre[j] + ex2;
        }
        if (tid == 0) scs[0] = 0.f;
        __syncthreads();

        // ---- box smooth via cumsum difference ----
        const int w = g_win[r];
        const float invw = 1.0f / (float)w;
        const int wh = w >> 1;
#pragma unroll
        for (int j = 0; j < SPT; ++j) {
            int t = base + j;
            int lo = t - wh;
            int hi = lo + w;
            lo = max(lo, 0);
            hi = min(hi, LL);
            sw[t] = (scs[hi] - scs[lo]) * invw;
        }
        __syncthreads();

        // ---- detrend b, normalize by max|.|, apply omit*scale ----
        const float b0 = sw[0], bl = sw[LL - 1];
        float mab = 0.f;
        float cc[SPT];
#pragma unroll
        for (int j = 0; j < SPT; ++j) {
            int t = base + j;
            float ft = (float)t * inv_lm1;
            float c = sw[t] - (b0 + (bl - b0) * ft);
            cc[j] = c;
            mab = fmaxf(mab, fabsf(c));
        }
        mab = block_reduce_max(mab, red, tid);
        const float denom = (mab == 0.f) ? 1.0f : mab;
        const float fac = g_omit[r] * g_scale[r] / denom;
#pragma unroll
        for (int j = 0; j < SPT; ++j) sw[base + j] = cc[j] * fac;
        __syncthreads();

        // ---- interp onto ppm axis; write real channel; fill FFT buffer ----
        const float istep = (float)(LL - 1) / (rhi - rlo);
        const size_t och = ((size_t)r * 2) * PP;
        for (int p = tid; p < PP; p += NT) {
            float xp = g_ppm[p];
            float v = 0.f;
            if (xp >= rlo && xp <= rhi) {
                float u = (xp - rlo) * istep;
                int i = (int)u;
                if (i > LL - 2) i = LL - 2;
                float f = u - (float)i;
                float s0 = sw[i], s1 = sw[i + 1];
                v = fmaf(s1 - s0, f, s0);
            }
            if (hh == 0) sf[PAD(p)].x = v;
            else         sf[PAD(p)].y = v;
            out[och + (PP - 1 - p)] = v;
            out[raw_off + och + p] = v;
        }
        __syncthreads();
    }

    // ========== Hilbert of both rows via one complex FFT (radix 16/16/16/2) ==========
    // ---- forward pass A: radix-16, h=512 ----
    {
        const int off = tid;
        float2 z[16];
#pragma unroll
        for (int m = 0; m < 16; ++m) z[m] = sf[PAD(off + (m << 9))];
        dft16_dif<false>(z);
        const float2 tb = d_tw[off];
        sf[PAD(off)] = z[0];
        float2 t = tb;
        sf[PAD(512 + off)] = cmulf(z[8], t);
#pragma unroll
        for (int q = 2; q < 16; ++q) {
            t = cmulf(t, tb);
            sf[PAD((q << 9) + off)] = cmulf(z[rv[q]], t);
        }
    }
    __syncthreads();

    // ---- forward pass B: radix-16, h=32 ----
    {
        const int off = tid & 31;
        const int b0 = (tid >> 5) << 9;
        float2 z[16];
#pragma unroll
        for (int m = 0; m < 16; ++m) z[m] = sf[PAD(b0 + off + (m << 5))];
        dft16_dif<false>(z);
        const float2 tb = d_tw[off << 4];
        sf[PAD(b0 + off)] = z[0];
        float2 t = tb;
        sf[PAD(b0 + 32 + off)] = cmulf(z[8], t);
#pragma unroll
        for (int q = 2; q < 16; ++q) {
            t = cmulf(t, tb);
            sf[PAD(b0 + (q << 5) + off)] = cmulf(z[rv[q]], t);
        }
    }
    __syncthreads();

    // ---- fused: fwd C (radix-16 h=2), fwd D (radix-2 h=1, shuffle),
    //      spectral multiply, inv D' (shuffle), inv C' (radix-16 h=2) ----
    {
        const int off = tid & 1;
        const int b0 = (tid >> 1) << 5;
        float2 z[16];
#pragma unroll
        for (int m = 0; m < 16; ++m) z[m] = sf[PAD(b0 + off + (m << 1))];
        dft16_dif<false>(z);
        {   // twiddle W32^{q*off} (identity for off==0)
            const float2 d = d_tw[256];
            const float2 tb = off ? d : make_float2(1.f, 0.f);
            float2 t = tb;
            z[8] = cmulf(z[8], t);
#pragma unroll
            for (int q = 2; q < 16; ++q) { t = cmulf(t, tb); z[rv[q]] = cmulf(z[rv[q]], t); }
        }
        const float s2 = off ? -1.f : 1.f;
        // fwd radix-2 (h=1) via shuffle with partner tid^1
#pragma unroll
        for (int k = 0; k < 16; ++k) {
            float px = __shfl_xor_sync(0xffffffffu, z[k].x, 1);
            float py = __shfl_xor_sync(0xffffffffu, z[k].y, 1);
            z[k].x = fmaf(s2, z[k].x, px);
            z[k].y = fmaf(s2, z[k].y, py);
        }
        // spectral multiply by -i*sgn(k); position p = b0 + 2*logical_r + off
#pragma unroll
        for (int k = 0; k < 16; ++k) {
            float zx = z[k].x, zy = z[k].y;
            z[k].x = off ? -zy : zy;
            z[k].y = off ? zx : -zx;
        }
        if (b0 == 0) { z[0].x = 0.f; z[0].y = 0.f; }   // p = 0 and p = 1
        // inv radix-2 (h=1) via shuffle
#pragma unroll
        for (int k = 0; k < 16; ++k) {
            float px = __shfl_xor_sync(0xffffffffu, z[k].x, 1);
            float py = __shfl_xor_sync(0xffffffffu, z[k].y, 1);
            z[k].x = fmaf(s2, z[k].x, px);
            z[k].y = fmaf(s2, z[k].y, py);
        }
        {   // inv C' pre-twiddle: x[m] (held in z[rv[m]]) *= W32^{-off*m}
            const float2 d = d_tw[256];
            const float2 tb = off ? make_float2(d.x, -d.y) : make_float2(1.f, 0.f);
            float2 t = tb;
            z[8] = cmulf(z[8], t);
#pragma unroll
            for (int m = 2; m < 16; ++m) { t = cmulf(t, tb); z[rv[m]] = cmulf(z[rv[m]], t); }
        }
        dft16_dit<true>(z);   // rev-in, natural-out
#pragma unroll
        for (int q = 0; q < 16; ++q) sf[PAD(b0 + off + (q << 1))] = z[q];
    }
    __syncthreads();

    // ---- inverse pass B': radix-16 DIT, h=32 ----
    {
        const int off = tid & 31;
        const int b0 = (tid >> 5) << 9;
        float2 z[16];
#pragma unroll
        for (int m = 0; m < 16; ++m) z[m] = sf[PAD(b0 + off + (m << 5))];
        const float2 d = d_tw[off << 4];
        const float2 tb = make_float2(d.x, -d.y);
        float2 t = tb;
        z[1] = cmulf(z[1], t);
#pragma unroll
        for (int m = 2; m < 16; ++m) { t = cmulf(t, tb); z[m] = cmulf(z[m], t); }
        dft16_dif<true>(z);
        sf[PAD(b0 + off)] = z[0];
#pragma unroll
        for (int q = 1; q < 16; ++q) sf[PAD(b0 + off + (q << 5))] = z[rv[q]];
    }
    __syncthreads();

    // ---- inverse pass A': radix-16 DIT, h=512; write gmem directly ----
    {
        const int off = tid;
        float2 z[16];
#pragma unroll
        for (int m = 0; m < 16; ++m) z[m] = sf[PAD(off + (m << 9))];
        const float2 d = d_tw[off];
        const float2 tb = make_float2(d.x, -d.y);
        float2 t = tb;
        z[1] = cmulf(z[1], t);
#pragma unroll
        for (int m = 2; m < 16; ++m) { t = cmulf(t, tb); z[m] = cmulf(z[m], t); }
        dft16_dif<true>(z);
        const float invP = 1.0f / (float)PP;
        const size_t ch1a = ((size_t)(2 * g) * 2 + 1) * PP;
        const size_t ch1b = ((size_t)(2 * g + 1) * 2 + 1) * PP;
#pragma unroll
        for (int q = 0; q < 16; ++q) {
            int p = off + (q << 9);
            float hA = z[rv[q]].x * invP;
            float hB = z[rv[q]].y * invP;
            out[ch1a + (PP - 1 - p)] = hA;
            out[raw_off + ch1a + p] = hA;
            out[ch1b + (PP - 1 - p)] = hB;
            out[raw_off + ch1b + p] = hB;
        }
    }
}

extern "C" void kernel_launch(void* const* d_in, const int* in_sizes, int n_in,
                              void* d_out, int out_size) {
    const float* g_start = (const float*)d_in[0];
    const float* g_end   = (const float*)d_in[1];
    const float* g_std   = (const float*)d_in[2];
    const float* g_lb    = (const float*)d_in[3];
    const float* g_ub    = (const float*)d_in[4];
    const int*   g_win   = (const int*)  d_in[5];
    const float* g_scale = (const float*)d_in[6];
    const float* g_noise = (const float*)d_in[7];
    const float* g_omit  = (const float*)d_in[8];
    const float* g_ppm   = (const float*)d_in[9];
    const float* g_range = (const float*)d_in[10];
    float* out = (float*)d_out;

    init_tw_kernel<<<(PP / 2 + 511) / 512, 512>>>();

    size_t smem = 69632 + sizeof(float) * (LL + (LL + 1) + 32);
    cudaFuncSetAttribute(pipeline_kernel,
                         cudaFuncAttributeMaxDynamicSharedMemorySize, (int)smem);
    pipeline_kernel<<<NB / 2, NT, smem>>>(
        g_start, g_end, g_std, g_lb, g_ub, g_win, g_scale, g_noise,
        g_omit, g_ppm, g_range, out);
}